// round 12
// baseline (speedup 1.0000x reference)
#include <cuda_runtime.h>
#include <cuda_bf16.h>
#include <cstdint>

// Problem constants
#define T_TOK   512
#define H_DIM   2048
#define I_DIM   1024
#define N_EXP   16
#define K_TOP   4
#define N_PAIR  (T_TOK * K_TOP)
#define QBS     128

#define CTA_M   128
#define CTA_N   64
#define KI      64        // fp32 K per iteration
#define NTHR    256

// SMEM blocks: rows x 128B (KI=64 bf16). A:128 rows, B:64 rows. hi+lo each.
#define ABLK    16384     // 128 x 128B
#define BBLK    8192      // 64 x 128B
#define BUF_BYTES  (2*ABLK + 2*BBLK)        // 48KB
#define SMEM_DYN   (2*BUF_BYTES + 256)      // double buffer -> ~96.25KB

// ---------------------------------------------------------------------------
// Scratch
// ---------------------------------------------------------------------------
__device__ int   g_off[N_EXP + 1];
__device__ int   g_pair[N_PAIR];
__device__ __align__(16) float g_hact[(N_PAIR + CTA_M) * I_DIM];

// ---------------------------------------------------------------------------
// Helpers
// ---------------------------------------------------------------------------
__device__ __forceinline__ uint32_t smem_u32(const void* p) {
    uint32_t a;
    asm("{ .reg .u64 t; cvta.to.shared.u64 t, %1; cvt.u32.u64 %0, t; }" : "=r"(a) : "l"(p));
    return a;
}

__device__ __forceinline__ void ldsm_x4(uint32_t* r, uint32_t addr) {
    asm volatile("ldmatrix.sync.aligned.m8n8.x4.shared.b16 {%0,%1,%2,%3}, [%4];"
        : "=r"(r[0]), "=r"(r[1]), "=r"(r[2]), "=r"(r[3]) : "r"(addr));
}
__device__ __forceinline__ void ldsm_x2(uint32_t* r, uint32_t addr) {
    asm volatile("ldmatrix.sync.aligned.m8n8.x2.shared.b16 {%0,%1}, [%2];"
        : "=r"(r[0]), "=r"(r[1]) : "r"(addr));
}

__device__ __forceinline__ void mma16816(float* c, const uint32_t* a, const uint32_t* b) {
    asm volatile(
        "mma.sync.aligned.m16n8k16.row.col.f32.bf16.bf16.f32 "
        "{%0,%1,%2,%3}, {%4,%5,%6,%7}, {%8,%9}, {%0,%1,%2,%3};"
        : "+f"(c[0]), "+f"(c[1]), "+f"(c[2]), "+f"(c[3])
        : "r"(a[0]), "r"(a[1]), "r"(a[2]), "r"(a[3]), "r"(b[0]), "r"(b[1]));
}

__device__ __forceinline__ void sts8(uint32_t addr, uint32_t v0, uint32_t v1) {
    asm volatile("st.shared.v2.b32 [%0], {%1,%2};" :: "r"(addr), "r"(v0), "r"(v1) : "memory");
}

// fp32x4 -> bf16 hi/lo, 8B to hi block + 8B to lo block; 128B-row XOR swizzle.
__device__ __forceinline__ void cvt_store(float4 v, int rb, int k0,
                                          uint32_t baseHi, uint32_t baseLo) {
    uint32_t chunk = (uint32_t)(k0 >> 3);
    uint32_t phys  = (uint32_t)rb * 128u + ((chunk ^ ((uint32_t)rb & 7u)) << 4) + ((k0 & 4) << 1);
    __nv_bfloat162 h0 = __floats2bfloat162_rn(v.x, v.y);
    __nv_bfloat162 h1 = __floats2bfloat162_rn(v.z, v.w);
    float rx = v.x - __bfloat162float(h0.x);
    float ry = v.y - __bfloat162float(h0.y);
    float rz = v.z - __bfloat162float(h1.x);
    float rw = v.w - __bfloat162float(h1.y);
    __nv_bfloat162 l0 = __floats2bfloat162_rn(rx, ry);
    __nv_bfloat162 l1 = __floats2bfloat162_rn(rz, rw);
    sts8(baseHi + phys, *(uint32_t*)&h0, *(uint32_t*)&h1);
    sts8(baseLo + phys, *(uint32_t*)&l0, *(uint32_t*)&l1);
}

// ---------------------------------------------------------------------------
// Kernel 0: routing (robust to int32/int64 selected_experts)
// ---------------------------------------------------------------------------
__global__ void route_kernel(const int* __restrict__ sel32)
{
    __shared__ int cnt[N_EXP];
    __shared__ int cur[N_EXP];
    __shared__ int is64;
    const int tid = threadIdx.x;

    if (tid == 0) is64 = 1;
    if (tid < N_EXP) cnt[tid] = 0;
    __syncthreads();

    for (int p = tid; p < N_PAIR / 2; p += NTHR)
        if (sel32[2 * p + 1] != 0) atomicExch(&is64, 0);
    __syncthreads();

    const int stride = is64 ? 2 : 1;
    for (int p = tid; p < N_PAIR; p += NTHR)
        atomicAdd(&cnt[sel32[(size_t)p * stride] & 15], 1);
    __syncthreads();

    if (tid == 0) {
        int acc = 0;
        for (int e = 0; e < N_EXP; e++) { g_off[e] = acc; cur[e] = acc; acc += cnt[e]; }
        g_off[N_EXP] = acc;
    }
    __syncthreads();

    for (int p = tid; p < N_PAIR; p += NTHR) {
        int e = sel32[(size_t)p * stride] & 15;
        g_pair[atomicAdd(&cur[e], 1)] = p;
    }
}

// ---------------------------------------------------------------------------
// Kernel 1: up-projection (bf16-split mma.sync). CTA 128 x 64.
// B rows interleave w0/w1: row r -> (r&1 ? w1 : w0) row (i0 + r/2);
// acc col pair (2j,2j+1) = (g_i, u_i). Epilogue: silu(g)*u -> g_hact.
// Tail M-tiles skip MMA fragments beyond mRows (16-row granularity).
// ---------------------------------------------------------------------------
__global__ __launch_bounds__(NTHR, 2)
void gemm1_kernel(const float* __restrict__ x,  const float* __restrict__ w0,
                  const float* __restrict__ w1, const float* __restrict__ s0,
                  const float* __restrict__ s1)
{
    const int e    = blockIdx.y;
    const int base = g_off[e];
    const int cntE = g_off[e + 1] - base;
    const int m0   = blockIdx.z * CTA_M;
    if (m0 >= cntE) return;
    const int mRows = min(CTA_M, cntE - m0);
    const int i0   = blockIdx.x * 32;      // 32 i per CTA (64 interleaved rows)

    extern __shared__ char dsm[];
    __shared__ int srow[CTA_M];
    const uint32_t sb = (smem_u32(dsm) + 127u) & ~127u;

    const int tid  = threadIdx.x;
    const int wid  = tid >> 5;
    const int lane = tid & 31;

    if (tid < CTA_M) {
        int mm = m0 + tid;
        srow[tid] = (mm < cntE) ? (g_pair[base + mm] / K_TOP) : 0;
    }
    __syncthreads();

    // A loader: 2 threads/row, 32 f32 each
    const int rbA = tid >> 1;
    const int khA = (tid & 1) * 32;
    const float* aSrc = x + (size_t)srow[rbA] * H_DIM + khA;
    // B loader: 4 threads/row, 16 f32 each
    const int rbB = tid >> 2;
    const int khB = (tid & 3) * 16;
    const int irow = i0 + (rbB >> 1);
    const float* bSrc = (rbB & 1)
        ? w1 + ((size_t)(e * I_DIM + irow)) * H_DIM + khB
        : w0 + ((size_t)(e * I_DIM + irow)) * H_DIM + khB;
    const float* sRow = ((rbB & 1) ? s1 : s0)
        + (size_t)(e * (I_DIM / QBS) + (i0 >> 7)) * (H_DIM / QBS);

    // compute mapping: 4 M-warps x 2 N-warps
    const int wm = wid & 3, wn = wid >> 2;
    const int mW = wm * 32, nW = wn * 32;
    const int arow = lane & 15;
    const int ahalf = lane >> 4;
    const int brow = lane & 7;
    const int bhalf = (lane >> 3) & 1;

    // active M-fragments for this warp (skip padding rows)
    const int nMf = (mW < mRows) ? ((mW + 16 < mRows) ? 2 : 1) : 0;

    float acc[2][4][4];
    #pragma unroll
    for (int a = 0; a < 2; a++)
        #pragma unroll
        for (int b = 0; b < 4; b++)
            #pragma unroll
            for (int c = 0; c < 4; c++) acc[a][b][c] = 0.f;

    const int NIT = H_DIM / KI;   // 32
    float4 aReg[8], bReg[4];

    // prologue: iter 0 -> buf 0
    {
        const float4* ap = (const float4*)aSrc;
        const float4* bp = (const float4*)bSrc;
        #pragma unroll
        for (int q = 0; q < 8; q++) aReg[q] = ap[q];
        #pragma unroll
        for (int q = 0; q < 4; q++) bReg[q] = bp[q];
        const float sc = sRow[0];
        #pragma unroll
        for (int q = 0; q < 8; q++)
            cvt_store(aReg[q], rbA, khA + q * 4, sb, sb + ABLK);
        #pragma unroll
        for (int q = 0; q < 4; q++) {
            float4 vb = bReg[q];
            vb.x *= sc; vb.y *= sc; vb.z *= sc; vb.w *= sc;
            cvt_store(vb, rbB, khB + q * 4, sb + 2 * ABLK, sb + 2 * ABLK + BBLK);
        }
    }
    __syncthreads();

    for (int it = 0; it < NIT; it++) {
        if (it + 1 < NIT) {
            const float4* ap = (const float4*)(aSrc + (it + 1) * KI);
            const float4* bp = (const float4*)(bSrc + (it + 1) * KI);
            #pragma unroll
            for (int q = 0; q < 8; q++) aReg[q] = ap[q];
            #pragma unroll
            for (int q = 0; q < 4; q++) bReg[q] = bp[q];
        }

        const uint32_t bufB = sb + (uint32_t)(it & 1) * BUF_BYTES;
        const uint32_t sbAhi = bufB, sbAlo = bufB + ABLK;
        const uint32_t sbBhi = bufB + 2 * ABLK, sbBlo = sbBhi + BBLK;

        #pragma unroll
        for (int ks = 0; ks < 4; ks++) {
            uint32_t aH[2][4], aL[2][4], bH[4][2], bL[4][2];
            #pragma unroll
            for (int mf = 0; mf < 2; mf++) if (mf < nMf) {
                uint32_t row = (uint32_t)(mW + mf * 16 + arow);
                uint32_t off = row * 128u + ((((uint32_t)(ks * 2 + ahalf)) ^ (row & 7u)) << 4);
                ldsm_x4(aH[mf], sbAhi + off);
                ldsm_x4(aL[mf], sbAlo + off);
            }
            #pragma unroll
            for (int nf = 0; nf < 4; nf++) {
                uint32_t row = (uint32_t)(nW + nf * 8 + brow);
                uint32_t off = row * 128u + ((((uint32_t)(ks * 2 + bhalf)) ^ (row & 7u)) << 4);
                ldsm_x2(bH[nf], sbBhi + off);
                ldsm_x2(bL[nf], sbBlo + off);
            }
            #pragma unroll
            for (int mf = 0; mf < 2; mf++) if (mf < nMf)
                #pragma unroll
                for (int nf = 0; nf < 4; nf++) {
                    mma16816(acc[mf][nf], aH[mf], bH[nf]);
                    mma16816(acc[mf][nf], aL[mf], bH[nf]);
                    mma16816(acc[mf][nf], aH[mf], bL[nf]);
                }
        }

        if (it + 1 < NIT) {
            const uint32_t nb = sb + (uint32_t)((it + 1) & 1) * BUF_BYTES;
            const float sc = sRow[(it + 1) >> 1];
            #pragma unroll
            for (int q = 0; q < 8; q++)
                cvt_store(aReg[q], rbA, khA + q * 4, nb, nb + ABLK);
            #pragma unroll
            for (int q = 0; q < 4; q++) {
                float4 vb = bReg[q];
                vb.x *= sc; vb.y *= sc; vb.z *= sc; vb.w *= sc;
                cvt_store(vb, rbB, khB + q * 4, nb + 2 * ABLK, nb + 2 * ABLK + BBLK);
            }
        }
        __syncthreads();
    }

    // epilogue: silu(g)*u, col pair (2j,2j+1) = (g,u) for i = i0 + wn*16 + nf*4 + qcol
    const int qrow = lane >> 2;
    const int qcol = lane & 3;
    #pragma unroll
    for (int mf = 0; mf < 2; mf++) if (mf < nMf) {
        const int r0 = mW + mf * 16 + qrow;
        const int r1 = r0 + 8;
        #pragma unroll
        for (int nf = 0; nf < 4; nf++) {
            const int ii = i0 + wn * 16 + nf * 4 + qcol;
            float g0 = acc[mf][nf][0], u0 = acc[mf][nf][1];
            float g1 = acc[mf][nf][2], u1 = acc[mf][nf][3];
            if (r0 < mRows) {
                float s = g0 / (1.0f + __expf(-g0));
                g_hact[(size_t)(base + m0 + r0) * I_DIM + ii] = s * u0;
            }
            if (r1 < mRows) {
                float s = g1 / (1.0f + __expf(-g1));
                g_hact[(size_t)(base + m0 + r1) * I_DIM + ii] = s * u1;
            }
        }
    }
}

// ---------------------------------------------------------------------------
// Kernel 2: down-projection (bf16-split mma.sync) + routing weight scatter.
// CTA 128 x 64 H-cols. Tail M-tiles skip MMA fragments beyond mRows.
// ---------------------------------------------------------------------------
__global__ __launch_bounds__(NTHR, 2)
void gemm2_kernel(const float* __restrict__ w2, const float* __restrict__ s2,
                  const float* __restrict__ rw, float* __restrict__ out)
{
    const int e    = blockIdx.y;
    const int base = g_off[e];
    const int cntE = g_off[e + 1] - base;
    const int m0   = blockIdx.z * CTA_M;
    if (m0 >= cntE) return;
    const int mRows = min(CTA_M, cntE - m0);
    const int n0   = blockIdx.x * CTA_N;

    extern __shared__ char dsm[];
    __shared__ int spair[CTA_M];
    const uint32_t sb = (smem_u32(dsm) + 127u) & ~127u;

    const int tid  = threadIdx.x;
    const int wid  = tid >> 5;
    const int lane = tid & 31;

    if (tid < CTA_M) {
        int mm = m0 + tid;
        spair[tid] = (mm < cntE) ? g_pair[base + mm] : 0;
    }
    __syncthreads();

    const int rbA = tid >> 1;
    const int khA = (tid & 1) * 32;
    const float* aSrc = g_hact + (size_t)(base + m0 + rbA) * I_DIM + khA;
    const int rbB = tid >> 2;
    const int khB = (tid & 3) * 16;
    const float* bSrc = w2 + ((size_t)(e * H_DIM + n0 + rbB)) * I_DIM + khB;
    const float* sRow = s2 + (size_t)(e * (H_DIM / QBS) + (n0 >> 7)) * (I_DIM / QBS);

    const int wm = wid & 3, wn = wid >> 2;
    const int mW = wm * 32, nW = wn * 32;
    const int arow = lane & 15;
    const int ahalf = lane >> 4;
    const int brow = lane & 7;
    const int bhalf = (lane >> 3) & 1;

    const int nMf = (mW < mRows) ? ((mW + 16 < mRows) ? 2 : 1) : 0;

    float acc[2][4][4];
    #pragma unroll
    for (int a = 0; a < 2; a++)
        #pragma unroll
        for (int b = 0; b < 4; b++)
            #pragma unroll
            for (int c = 0; c < 4; c++) acc[a][b][c] = 0.f;

    const int NIT = I_DIM / KI;   // 16
    float4 aReg[8], bReg[4];

    {
        const float4* ap = (const float4*)aSrc;
        const float4* bp = (const float4*)bSrc;
        #pragma unroll
        for (int q = 0; q < 8; q++) aReg[q] = ap[q];
        #pragma unroll
        for (int q = 0; q < 4; q++) bReg[q] = bp[q];
        const float sc = sRow[0];
        #pragma unroll
        for (int q = 0; q < 8; q++)
            cvt_store(aReg[q], rbA, khA + q * 4, sb, sb + ABLK);
        #pragma unroll
        for (int q = 0; q < 4; q++) {
            float4 vb = bReg[q];
            vb.x *= sc; vb.y *= sc; vb.z *= sc; vb.w *= sc;
            cvt_store(vb, rbB, khB + q * 4, sb + 2 * ABLK, sb + 2 * ABLK + BBLK);
        }
    }
    __syncthreads();

    for (int it = 0; it < NIT; it++) {
        if (it + 1 < NIT) {
            const float4* ap = (const float4*)(aSrc + (it + 1) * KI);
            const float4* bp = (const float4*)(bSrc + (it + 1) * KI);
            #pragma unroll
            for (int q = 0; q < 8; q++) aReg[q] = ap[q];
            #pragma unroll
            for (int q = 0; q < 4; q++) bReg[q] = bp[q];
        }

        const uint32_t bufB = sb + (uint32_t)(it & 1) * BUF_BYTES;
        const uint32_t sbAhi = bufB, sbAlo = bufB + ABLK;
        const uint32_t sbBhi = bufB + 2 * ABLK, sbBlo = sbBhi + BBLK;

        #pragma unroll
        for (int ks = 0; ks < 4; ks++) {
            uint32_t aH[2][4], aL[2][4], bH[4][2], bL[4][2];
            #pragma unroll
            for (int mf = 0; mf < 2; mf++) if (mf < nMf) {
                uint32_t row = (uint32_t)(mW + mf * 16 + arow);
                uint32_t off = row * 128u + ((((uint32_t)(ks * 2 + ahalf)) ^ (row & 7u)) << 4);
                ldsm_x4(aH[mf], sbAhi + off);
                ldsm_x4(aL[mf], sbAlo + off);
            }
            #pragma unroll
            for (int nf = 0; nf < 4; nf++) {
                uint32_t row = (uint32_t)(nW + nf * 8 + brow);
                uint32_t off = row * 128u + ((((uint32_t)(ks * 2 + bhalf)) ^ (row & 7u)) << 4);
                ldsm_x2(bH[nf], sbBhi + off);
                ldsm_x2(bL[nf], sbBlo + off);
            }
            #pragma unroll
            for (int mf = 0; mf < 2; mf++) if (mf < nMf)
                #pragma unroll
                for (int nf = 0; nf < 4; nf++) {
                    mma16816(acc[mf][nf], aH[mf], bH[nf]);
                    mma16816(acc[mf][nf], aL[mf], bH[nf]);
                    mma16816(acc[mf][nf], aH[mf], bL[nf]);
                }
        }

        if (it + 1 < NIT) {
            const uint32_t nb = sb + (uint32_t)((it + 1) & 1) * BUF_BYTES;
            const float sc = sRow[(it + 1) >> 1];
            #pragma unroll
            for (int q = 0; q < 8; q++)
                cvt_store(aReg[q], rbA, khA + q * 4, nb, nb + ABLK);
            #pragma unroll
            for (int q = 0; q < 4; q++) {
                float4 vb = bReg[q];
                vb.x *= sc; vb.y *= sc; vb.z *= sc; vb.w *= sc;
                cvt_store(vb, rbB, khB + q * 4, nb + 2 * ABLK, nb + 2 * ABLK + BBLK);
            }
        }
        __syncthreads();
    }

    // epilogue: routing weight, scatter
    const int qrow = lane >> 2;
    const int qcol = lane & 3;
    #pragma unroll
    for (int mf = 0; mf < 2; mf++) if (mf < nMf) {
        const int r0 = mW + mf * 16 + qrow;
        const int r1 = r0 + 8;
        const int pid0 = spair[r0];
        const int pid1 = spair[r1];
        const float w0g = rw[pid0];
        const float w1g = rw[pid1];
        #pragma unroll
        for (int nf = 0; nf < 4; nf++) {
            const int col = n0 + nW + nf * 8 + qcol * 2;
            if (r0 < mRows) {
                float2 v = { acc[mf][nf][0] * w0g, acc[mf][nf][1] * w0g };
                *(float2*)&out[(size_t)pid0 * H_DIM + col] = v;
            }
            if (r1 < mRows) {
                float2 v = { acc[mf][nf][2] * w1g, acc[mf][nf][3] * w1g };
                *(float2*)&out[(size_t)pid1 * H_DIM + col] = v;
            }
        }
    }
}

// ---------------------------------------------------------------------------
// Launch
// ---------------------------------------------------------------------------
extern "C" void kernel_launch(void* const* d_in, const int* in_sizes, int n_in,
                              void* d_out, int out_size)
{
    const float* x   = (const float*)d_in[0];
    const float* w0  = (const float*)d_in[1];
    const float* w1  = (const float*)d_in[2];
    const float* w2  = (const float*)d_in[3];
    const float* s0  = (const float*)d_in[4];
    const float* s1  = (const float*)d_in[5];
    const float* s2  = (const float*)d_in[6];
    const int*   sel = (const int*)  d_in[7];
    const float* rw  = (const float*)d_in[8];
    float*       out = (float*)d_out;

    cudaFuncSetAttribute(gemm1_kernel, cudaFuncAttributeMaxDynamicSharedMemorySize, SMEM_DYN);
    cudaFuncSetAttribute(gemm2_kernel, cudaFuncAttributeMaxDynamicSharedMemorySize, SMEM_DYN);

    route_kernel<<<1, NTHR>>>(sel);

    dim3 g1(I_DIM / 32, N_EXP, N_PAIR / CTA_M);    // 32 x 16 x 16 (z early-exits)
    gemm1_kernel<<<g1, NTHR, SMEM_DYN>>>(x, w0, w1, s0, s1);

    dim3 g2(H_DIM / CTA_N, N_EXP, N_PAIR / CTA_M); // 32 x 16 x 16
    gemm2_kernel<<<g2, NTHR, SMEM_DYN>>>(w2, s2, rw, out);
}

// round 14
// speedup vs baseline: 1.1149x; 1.1149x over previous
#include <cuda_runtime.h>
#include <cuda_bf16.h>
#include <cstdint>

// Problem constants
#define T_TOK   512
#define H_DIM   2048
#define I_DIM   1024
#define N_EXP   16
#define K_TOP   4
#define N_PAIR  (T_TOK * K_TOP)
#define QBS     128

#define CTA_M   128
#define CTA_N   64
#define KI      64        // fp32 K per iteration
#define NTHR    256

// SMEM blocks: rows x 128B (KI=64 bf16). A:128 rows, B:64 rows. hi+lo each.
#define ABLK    16384     // 128 x 128B
#define BBLK    8192      // 64 x 128B
#define BUF_BYTES  (2*ABLK + 2*BBLK)        // 48KB
#define SMEM_DYN   (2*BUF_BYTES + 256)      // double buffer -> ~96.25KB

// ---------------------------------------------------------------------------
// Scratch
// ---------------------------------------------------------------------------
__device__ int   g_off[N_EXP + 1];
__device__ int   g_pair[N_PAIR];
__device__ __align__(16) float g_hact[(N_PAIR + CTA_M) * I_DIM];

// ---------------------------------------------------------------------------
// Helpers
// ---------------------------------------------------------------------------
__device__ __forceinline__ uint32_t smem_u32(const void* p) {
    uint32_t a;
    asm("{ .reg .u64 t; cvta.to.shared.u64 t, %1; cvt.u32.u64 %0, t; }" : "=r"(a) : "l"(p));
    return a;
}

__device__ __forceinline__ void ldsm_x4(uint32_t* r, uint32_t addr) {
    asm volatile("ldmatrix.sync.aligned.m8n8.x4.shared.b16 {%0,%1,%2,%3}, [%4];"
        : "=r"(r[0]), "=r"(r[1]), "=r"(r[2]), "=r"(r[3]) : "r"(addr));
}
__device__ __forceinline__ void ldsm_x2(uint32_t* r, uint32_t addr) {
    asm volatile("ldmatrix.sync.aligned.m8n8.x2.shared.b16 {%0,%1}, [%2];"
        : "=r"(r[0]), "=r"(r[1]) : "r"(addr));
}

__device__ __forceinline__ void mma16816(float* c, const uint32_t* a, const uint32_t* b) {
    asm volatile(
        "mma.sync.aligned.m16n8k16.row.col.f32.bf16.bf16.f32 "
        "{%0,%1,%2,%3}, {%4,%5,%6,%7}, {%8,%9}, {%0,%1,%2,%3};"
        : "+f"(c[0]), "+f"(c[1]), "+f"(c[2]), "+f"(c[3])
        : "r"(a[0]), "r"(a[1]), "r"(a[2]), "r"(a[3]), "r"(b[0]), "r"(b[1]));
}

__device__ __forceinline__ void sts8(uint32_t addr, uint32_t v0, uint32_t v1) {
    asm volatile("st.shared.v2.b32 [%0], {%1,%2};" :: "r"(addr), "r"(v0), "r"(v1) : "memory");
}

// fp32x4 -> bf16 hi/lo, 8B to hi block + 8B to lo block; 128B-row XOR swizzle.
__device__ __forceinline__ void cvt_store(float4 v, int rb, int k0,
                                          uint32_t baseHi, uint32_t baseLo) {
    uint32_t chunk = (uint32_t)(k0 >> 3);
    uint32_t phys  = (uint32_t)rb * 128u + ((chunk ^ ((uint32_t)rb & 7u)) << 4) + ((k0 & 4) << 1);
    __nv_bfloat162 h0 = __floats2bfloat162_rn(v.x, v.y);
    __nv_bfloat162 h1 = __floats2bfloat162_rn(v.z, v.w);
    float rx = v.x - __bfloat162float(h0.x);
    float ry = v.y - __bfloat162float(h0.y);
    float rz = v.z - __bfloat162float(h1.x);
    float rw = v.w - __bfloat162float(h1.y);
    __nv_bfloat162 l0 = __floats2bfloat162_rn(rx, ry);
    __nv_bfloat162 l1 = __floats2bfloat162_rn(rz, rw);
    sts8(baseHi + phys, *(uint32_t*)&h0, *(uint32_t*)&h1);
    sts8(baseLo + phys, *(uint32_t*)&l0, *(uint32_t*)&l1);
}

// ---------------------------------------------------------------------------
// Kernel 0: routing (robust to int32/int64 selected_experts)
// ---------------------------------------------------------------------------
__global__ void route_kernel(const int* __restrict__ sel32)
{
    __shared__ int cnt[N_EXP];
    __shared__ int cur[N_EXP];
    __shared__ int is64;
    const int tid = threadIdx.x;

    if (tid == 0) is64 = 1;
    if (tid < N_EXP) cnt[tid] = 0;
    __syncthreads();

    for (int p = tid; p < N_PAIR / 2; p += NTHR)
        if (sel32[2 * p + 1] != 0) atomicExch(&is64, 0);
    __syncthreads();

    const int stride = is64 ? 2 : 1;
    for (int p = tid; p < N_PAIR; p += NTHR)
        atomicAdd(&cnt[sel32[(size_t)p * stride] & 15], 1);
    __syncthreads();

    if (tid == 0) {
        int acc = 0;
        for (int e = 0; e < N_EXP; e++) { g_off[e] = acc; cur[e] = acc; acc += cnt[e]; }
        g_off[N_EXP] = acc;
    }
    __syncthreads();

    for (int p = tid; p < N_PAIR; p += NTHR) {
        int e = sel32[(size_t)p * stride] & 15;
        g_pair[atomicAdd(&cur[e], 1)] = p;
    }
}

// ---------------------------------------------------------------------------
// Kernel 1: up-projection (bf16-split mma.sync). CTA 128 x 64.
// B rows interleave w0/w1: row r -> (r&1 ? w1 : w0) row (i0 + r/2);
// acc col pair (2j,2j+1) = (g_i, u_i). Epilogue: silu(g)*u -> g_hact.
// Tail tiles: skip A-producer work for rows >= mRows, skip all frag work
// in warps with no valid M-fragment.
// ---------------------------------------------------------------------------
__global__ __launch_bounds__(NTHR, 2)
void gemm1_kernel(const float* __restrict__ x,  const float* __restrict__ w0,
                  const float* __restrict__ w1, const float* __restrict__ s0,
                  const float* __restrict__ s1)
{
    const int e    = blockIdx.y;
    const int base = g_off[e];
    const int cntE = g_off[e + 1] - base;
    const int m0   = blockIdx.z * CTA_M;
    if (m0 >= cntE) return;
    const int mRows = min(CTA_M, cntE - m0);
    const int i0   = blockIdx.x * 32;      // 32 i per CTA (64 interleaved rows)

    extern __shared__ char dsm[];
    __shared__ int srow[CTA_M];
    const uint32_t sb = (smem_u32(dsm) + 127u) & ~127u;

    const int tid  = threadIdx.x;
    const int wid  = tid >> 5;
    const int lane = tid & 31;

    if (tid < CTA_M) {
        int mm = m0 + tid;
        srow[tid] = (mm < cntE) ? (g_pair[base + mm] / K_TOP) : 0;
    }
    __syncthreads();

    // A loader: 2 threads/row, 32 f32 each; inactive if row is padding
    const int rbA = tid >> 1;
    const int khA = (tid & 1) * 32;
    const bool aAct = (rbA < mRows);
    const float* aSrc = x + (size_t)srow[rbA] * H_DIM + khA;
    // B loader: 4 threads/row, 16 f32 each
    const int rbB = tid >> 2;
    const int khB = (tid & 3) * 16;
    const int irow = i0 + (rbB >> 1);
    const float* bSrc = (rbB & 1)
        ? w1 + ((size_t)(e * I_DIM + irow)) * H_DIM + khB
        : w0 + ((size_t)(e * I_DIM + irow)) * H_DIM + khB;
    const float* sRow = ((rbB & 1) ? s1 : s0)
        + (size_t)(e * (I_DIM / QBS) + (i0 >> 7)) * (H_DIM / QBS);

    // compute mapping: 4 M-warps x 2 N-warps
    const int wm = wid & 3, wn = wid >> 2;
    const int mW = wm * 32, nW = wn * 32;
    const int arow = lane & 15;
    const int ahalf = lane >> 4;
    const int brow = lane & 7;
    const int bhalf = (lane >> 3) & 1;

    // active M-fragments for this warp (skip padding rows)
    const int nMf = (mW < mRows) ? ((mW + 16 < mRows) ? 2 : 1) : 0;

    float acc[2][4][4];
    #pragma unroll
    for (int a = 0; a < 2; a++)
        #pragma unroll
        for (int b = 0; b < 4; b++)
            #pragma unroll
            for (int c = 0; c < 4; c++) acc[a][b][c] = 0.f;

    const int NIT = H_DIM / KI;   // 32
    float4 aReg[8], bReg[4];

    // prologue: iter 0 -> buf 0
    {
        if (aAct) {
            const float4* ap = (const float4*)aSrc;
            #pragma unroll
            for (int q = 0; q < 8; q++) aReg[q] = ap[q];
            #pragma unroll
            for (int q = 0; q < 8; q++)
                cvt_store(aReg[q], rbA, khA + q * 4, sb, sb + ABLK);
        }
        const float4* bp = (const float4*)bSrc;
        #pragma unroll
        for (int q = 0; q < 4; q++) bReg[q] = bp[q];
        const float sc = sRow[0];
        #pragma unroll
        for (int q = 0; q < 4; q++) {
            float4 vb = bReg[q];
            vb.x *= sc; vb.y *= sc; vb.z *= sc; vb.w *= sc;
            cvt_store(vb, rbB, khB + q * 4, sb + 2 * ABLK, sb + 2 * ABLK + BBLK);
        }
    }
    __syncthreads();

    for (int it = 0; it < NIT; it++) {
        if (it + 1 < NIT) {
            if (aAct) {
                const float4* ap = (const float4*)(aSrc + (it + 1) * KI);
                #pragma unroll
                for (int q = 0; q < 8; q++) aReg[q] = ap[q];
            }
            const float4* bp = (const float4*)(bSrc + (it + 1) * KI);
            #pragma unroll
            for (int q = 0; q < 4; q++) bReg[q] = bp[q];
        }

        const uint32_t bufB = sb + (uint32_t)(it & 1) * BUF_BYTES;
        const uint32_t sbAhi = bufB, sbAlo = bufB + ABLK;
        const uint32_t sbBhi = bufB + 2 * ABLK, sbBlo = sbBhi + BBLK;

        if (nMf) {
            #pragma unroll
            for (int ks = 0; ks < 4; ks++) {
                uint32_t aH[2][4], aL[2][4], bH[4][2], bL[4][2];
                #pragma unroll
                for (int mf = 0; mf < 2; mf++) if (mf < nMf) {
                    uint32_t row = (uint32_t)(mW + mf * 16 + arow);
                    uint32_t off = row * 128u + ((((uint32_t)(ks * 2 + ahalf)) ^ (row & 7u)) << 4);
                    ldsm_x4(aH[mf], sbAhi + off);
                    ldsm_x4(aL[mf], sbAlo + off);
                }
                #pragma unroll
                for (int nf = 0; nf < 4; nf++) {
                    uint32_t row = (uint32_t)(nW + nf * 8 + brow);
                    uint32_t off = row * 128u + ((((uint32_t)(ks * 2 + bhalf)) ^ (row & 7u)) << 4);
                    ldsm_x2(bH[nf], sbBhi + off);
                    ldsm_x2(bL[nf], sbBlo + off);
                }
                #pragma unroll
                for (int mf = 0; mf < 2; mf++) if (mf < nMf)
                    #pragma unroll
                    for (int nf = 0; nf < 4; nf++) {
                        mma16816(acc[mf][nf], aH[mf], bH[nf]);
                        mma16816(acc[mf][nf], aL[mf], bH[nf]);
                        mma16816(acc[mf][nf], aH[mf], bL[nf]);
                    }
            }
        }

        if (it + 1 < NIT) {
            const uint32_t nb = sb + (uint32_t)((it + 1) & 1) * BUF_BYTES;
            const float sc = sRow[(it + 1) >> 1];
            if (aAct) {
                #pragma unroll
                for (int q = 0; q < 8; q++)
                    cvt_store(aReg[q], rbA, khA + q * 4, nb, nb + ABLK);
            }
            #pragma unroll
            for (int q = 0; q < 4; q++) {
                float4 vb = bReg[q];
                vb.x *= sc; vb.y *= sc; vb.z *= sc; vb.w *= sc;
                cvt_store(vb, rbB, khB + q * 4, nb + 2 * ABLK, nb + 2 * ABLK + BBLK);
            }
        }
        __syncthreads();
    }

    // epilogue: silu(g)*u, col pair (2j,2j+1) = (g,u) for i = i0 + wn*16 + nf*4 + qcol
    const int qrow = lane >> 2;
    const int qcol = lane & 3;
    #pragma unroll
    for (int mf = 0; mf < 2; mf++) if (mf < nMf) {
        const int r0 = mW + mf * 16 + qrow;
        const int r1 = r0 + 8;
        #pragma unroll
        for (int nf = 0; nf < 4; nf++) {
            const int ii = i0 + wn * 16 + nf * 4 + qcol;
            float g0 = acc[mf][nf][0], u0 = acc[mf][nf][1];
            float g1 = acc[mf][nf][2], u1 = acc[mf][nf][3];
            if (r0 < mRows) {
                float s = g0 / (1.0f + __expf(-g0));
                g_hact[(size_t)(base + m0 + r0) * I_DIM + ii] = s * u0;
            }
            if (r1 < mRows) {
                float s = g1 / (1.0f + __expf(-g1));
                g_hact[(size_t)(base + m0 + r1) * I_DIM + ii] = s * u1;
            }
        }
    }
}

// ---------------------------------------------------------------------------
// Kernel 2: down-projection (bf16-split mma.sync) + routing weight scatter.
// CTA 128 x 64 H-cols. Same tail-tile work skipping.
// ---------------------------------------------------------------------------
__global__ __launch_bounds__(NTHR, 2)
void gemm2_kernel(const float* __restrict__ w2, const float* __restrict__ s2,
                  const float* __restrict__ rw, float* __restrict__ out)
{
    const int e    = blockIdx.y;
    const int base = g_off[e];
    const int cntE = g_off[e + 1] - base;
    const int m0   = blockIdx.z * CTA_M;
    if (m0 >= cntE) return;
    const int mRows = min(CTA_M, cntE - m0);
    const int n0   = blockIdx.x * CTA_N;

    extern __shared__ char dsm[];
    __shared__ int spair[CTA_M];
    const uint32_t sb = (smem_u32(dsm) + 127u) & ~127u;

    const int tid  = threadIdx.x;
    const int wid  = tid >> 5;
    const int lane = tid & 31;

    if (tid < CTA_M) {
        int mm = m0 + tid;
        spair[tid] = (mm < cntE) ? g_pair[base + mm] : 0;
    }
    __syncthreads();

    const int rbA = tid >> 1;
    const int khA = (tid & 1) * 32;
    const bool aAct = (rbA < mRows);
    const float* aSrc = g_hact + (size_t)(base + m0 + rbA) * I_DIM + khA;
    const int rbB = tid >> 2;
    const int khB = (tid & 3) * 16;
    const float* bSrc = w2 + ((size_t)(e * H_DIM + n0 + rbB)) * I_DIM + khB;
    const float* sRow = s2 + (size_t)(e * (H_DIM / QBS) + (n0 >> 7)) * (I_DIM / QBS);

    const int wm = wid & 3, wn = wid >> 2;
    const int mW = wm * 32, nW = wn * 32;
    const int arow = lane & 15;
    const int ahalf = lane >> 4;
    const int brow = lane & 7;
    const int bhalf = (lane >> 3) & 1;

    const int nMf = (mW < mRows) ? ((mW + 16 < mRows) ? 2 : 1) : 0;

    float acc[2][4][4];
    #pragma unroll
    for (int a = 0; a < 2; a++)
        #pragma unroll
        for (int b = 0; b < 4; b++)
            #pragma unroll
            for (int c = 0; c < 4; c++) acc[a][b][c] = 0.f;

    const int NIT = I_DIM / KI;   // 16
    float4 aReg[8], bReg[4];

    {
        if (aAct) {
            const float4* ap = (const float4*)aSrc;
            #pragma unroll
            for (int q = 0; q < 8; q++) aReg[q] = ap[q];
            #pragma unroll
            for (int q = 0; q < 8; q++)
                cvt_store(aReg[q], rbA, khA + q * 4, sb, sb + ABLK);
        }
        const float4* bp = (const float4*)bSrc;
        #pragma unroll
        for (int q = 0; q < 4; q++) bReg[q] = bp[q];
        const float sc = sRow[0];
        #pragma unroll
        for (int q = 0; q < 4; q++) {
            float4 vb = bReg[q];
            vb.x *= sc; vb.y *= sc; vb.z *= sc; vb.w *= sc;
            cvt_store(vb, rbB, khB + q * 4, sb + 2 * ABLK, sb + 2 * ABLK + BBLK);
        }
    }
    __syncthreads();

    for (int it = 0; it < NIT; it++) {
        if (it + 1 < NIT) {
            if (aAct) {
                const float4* ap = (const float4*)(aSrc + (it + 1) * KI);
                #pragma unroll
                for (int q = 0; q < 8; q++) aReg[q] = ap[q];
            }
            const float4* bp = (const float4*)(bSrc + (it + 1) * KI);
            #pragma unroll
            for (int q = 0; q < 4; q++) bReg[q] = bp[q];
        }

        const uint32_t bufB = sb + (uint32_t)(it & 1) * BUF_BYTES;
        const uint32_t sbAhi = bufB, sbAlo = bufB + ABLK;
        const uint32_t sbBhi = bufB + 2 * ABLK, sbBlo = sbBhi + BBLK;

        if (nMf) {
            #pragma unroll
            for (int ks = 0; ks < 4; ks++) {
                uint32_t aH[2][4], aL[2][4], bH[4][2], bL[4][2];
                #pragma unroll
                for (int mf = 0; mf < 2; mf++) if (mf < nMf) {
                    uint32_t row = (uint32_t)(mW + mf * 16 + arow);
                    uint32_t off = row * 128u + ((((uint32_t)(ks * 2 + ahalf)) ^ (row & 7u)) << 4);
                    ldsm_x4(aH[mf], sbAhi + off);
                    ldsm_x4(aL[mf], sbAlo + off);
                }
                #pragma unroll
                for (int nf = 0; nf < 4; nf++) {
                    uint32_t row = (uint32_t)(nW + nf * 8 + brow);
                    uint32_t off = row * 128u + ((((uint32_t)(ks * 2 + bhalf)) ^ (row & 7u)) << 4);
                    ldsm_x2(bH[nf], sbBhi + off);
                    ldsm_x2(bL[nf], sbBlo + off);
                }
                #pragma unroll
                for (int mf = 0; mf < 2; mf++) if (mf < nMf)
                    #pragma unroll
                    for (int nf = 0; nf < 4; nf++) {
                        mma16816(acc[mf][nf], aH[mf], bH[nf]);
                        mma16816(acc[mf][nf], aL[mf], bH[nf]);
                        mma16816(acc[mf][nf], aH[mf], bL[nf]);
                    }
            }
        }

        if (it + 1 < NIT) {
            const uint32_t nb = sb + (uint32_t)((it + 1) & 1) * BUF_BYTES;
            const float sc = sRow[(it + 1) >> 1];
            if (aAct) {
                #pragma unroll
                for (int q = 0; q < 8; q++)
                    cvt_store(aReg[q], rbA, khA + q * 4, nb, nb + ABLK);
            }
            #pragma unroll
            for (int q = 0; q < 4; q++) {
                float4 vb = bReg[q];
                vb.x *= sc; vb.y *= sc; vb.z *= sc; vb.w *= sc;
                cvt_store(vb, rbB, khB + q * 4, nb + 2 * ABLK, nb + 2 * ABLK + BBLK);
            }
        }
        __syncthreads();
    }

    // epilogue: routing weight, scatter
    const int qrow = lane >> 2;
    const int qcol = lane & 3;
    #pragma unroll
    for (int mf = 0; mf < 2; mf++) if (mf < nMf) {
        const int r0 = mW + mf * 16 + qrow;
        const int r1 = r0 + 8;
        const int pid0 = spair[r0];
        const int pid1 = spair[r1];
        const float w0g = rw[pid0];
        const float w1g = rw[pid1];
        #pragma unroll
        for (int nf = 0; nf < 4; nf++) {
            const int col = n0 + nW + nf * 8 + qcol * 2;
            if (r0 < mRows) {
                float2 v = { acc[mf][nf][0] * w0g, acc[mf][nf][1] * w0g };
                *(float2*)&out[(size_t)pid0 * H_DIM + col] = v;
            }
            if (r1 < mRows) {
                float2 v = { acc[mf][nf][2] * w1g, acc[mf][nf][3] * w1g };
                *(float2*)&out[(size_t)pid1 * H_DIM + col] = v;
            }
        }
    }
}

// ---------------------------------------------------------------------------
// Launch
// ---------------------------------------------------------------------------
extern "C" void kernel_launch(void* const* d_in, const int* in_sizes, int n_in,
                              void* d_out, int out_size)
{
    const float* x   = (const float*)d_in[0];
    const float* w0  = (const float*)d_in[1];
    const float* w1  = (const float*)d_in[2];
    const float* w2  = (const float*)d_in[3];
    const float* s0  = (const float*)d_in[4];
    const float* s1  = (const float*)d_in[5];
    const float* s2  = (const float*)d_in[6];
    const int*   sel = (const int*)  d_in[7];
    const float* rw  = (const float*)d_in[8];
    float*       out = (float*)d_out;

    cudaFuncSetAttribute(gemm1_kernel, cudaFuncAttributeMaxDynamicSharedMemorySize, SMEM_DYN);
    cudaFuncSetAttribute(gemm2_kernel, cudaFuncAttributeMaxDynamicSharedMemorySize, SMEM_DYN);

    route_kernel<<<1, NTHR>>>(sel);

    dim3 g1(I_DIM / 32, N_EXP, N_PAIR / CTA_M);    // 32 x 16 x 16 (z early-exits)
    gemm1_kernel<<<g1, NTHR, SMEM_DYN>>>(x, w0, w1, s0, s1);

    dim3 g2(H_DIM / CTA_N, N_EXP, N_PAIR / CTA_M); // 32 x 16 x 16
    gemm2_kernel<<<g2, NTHR, SMEM_DYN>>>(w2, s2, rw, out);
}

// round 16
// speedup vs baseline: 1.3353x; 1.1977x over previous
#include <cuda_runtime.h>
#include <cuda_fp16.h>
#include <cstdint>

// Problem constants
#define T_TOK   512
#define H_DIM   2048
#define I_DIM   1024
#define N_EXP   16
#define K_TOP   4
#define N_PAIR  (T_TOK * K_TOP)
#define QBS     128

#define CTA_M   128
#define CTA_N   64
#define KI      64        // fp32 K per iteration
#define NTHR    256

// SMEM: A single fp16 block (128 x 128B); B split hi/lo (64 x 128B each)
#define ABLK    16384
#define BBLK    8192
#define BUF_BYTES  (ABLK + 2*BBLK)          // 32KB
#define SMEM_DYN   (2*BUF_BYTES + 256)      // double buffer ~64.25KB

// ---------------------------------------------------------------------------
// Scratch
// ---------------------------------------------------------------------------
__device__ int   g_off[N_EXP + 1];
__device__ int   g_pair[N_PAIR];
__device__ __align__(16) float g_hact[(N_PAIR + CTA_M) * I_DIM];

// ---------------------------------------------------------------------------
// Helpers
// ---------------------------------------------------------------------------
__device__ __forceinline__ uint32_t smem_u32(const void* p) {
    uint32_t a;
    asm("{ .reg .u64 t; cvta.to.shared.u64 t, %1; cvt.u32.u64 %0, t; }" : "=r"(a) : "l"(p));
    return a;
}

__device__ __forceinline__ void ldsm_x4(uint32_t* r, uint32_t addr) {
    asm volatile("ldmatrix.sync.aligned.m8n8.x4.shared.b16 {%0,%1,%2,%3}, [%4];"
        : "=r"(r[0]), "=r"(r[1]), "=r"(r[2]), "=r"(r[3]) : "r"(addr));
}
__device__ __forceinline__ void ldsm_x2(uint32_t* r, uint32_t addr) {
    asm volatile("ldmatrix.sync.aligned.m8n8.x2.shared.b16 {%0,%1}, [%2];"
        : "=r"(r[0]), "=r"(r[1]) : "r"(addr));
}

__device__ __forceinline__ void mma16816f(float* c, const uint32_t* a, const uint32_t* b) {
    asm volatile(
        "mma.sync.aligned.m16n8k16.row.col.f32.f16.f16.f32 "
        "{%0,%1,%2,%3}, {%4,%5,%6,%7}, {%8,%9}, {%0,%1,%2,%3};"
        : "+f"(c[0]), "+f"(c[1]), "+f"(c[2]), "+f"(c[3])
        : "r"(a[0]), "r"(a[1]), "r"(a[2]), "r"(a[3]), "r"(b[0]), "r"(b[1]));
}

__device__ __forceinline__ void sts8(uint32_t addr, uint32_t v0, uint32_t v1) {
    asm volatile("st.shared.v2.b32 [%0], {%1,%2};" :: "r"(addr), "r"(v0), "r"(v1) : "memory");
}

__device__ __forceinline__ uint32_t swzoff(int rb, int k0) {
    uint32_t chunk = (uint32_t)(k0 >> 3);
    return (uint32_t)rb * 128u + ((chunk ^ ((uint32_t)rb & 7u)) << 4) + ((k0 & 4) << 1);
}

// A: fp32x4 -> single fp16 quad (8B)
__device__ __forceinline__ void cvtA_store(float4 v, int rb, int k0, uint32_t base) {
    uint32_t phys = swzoff(rb, k0);
    __half2 h0 = __floats2half2_rn(v.x, v.y);
    __half2 h1 = __floats2half2_rn(v.z, v.w);
    sts8(base + phys, *(uint32_t*)&h0, *(uint32_t*)&h1);
}

// B: fp32x4 -> fp16 hi quad + fp16 lo (residual) quad
__device__ __forceinline__ void cvtB_store(float4 v, int rb, int k0,
                                           uint32_t baseHi, uint32_t baseLo) {
    uint32_t phys = swzoff(rb, k0);
    __half2 h0 = __floats2half2_rn(v.x, v.y);
    __half2 h1 = __floats2half2_rn(v.z, v.w);
    float rx = v.x - __half2float(__low2half(h0));
    float ry = v.y - __half2float(__high2half(h0));
    float rz = v.z - __half2float(__low2half(h1));
    float rw = v.w - __half2float(__high2half(h1));
    __half2 l0 = __floats2half2_rn(rx, ry);
    __half2 l1 = __floats2half2_rn(rz, rw);
    sts8(baseHi + phys, *(uint32_t*)&h0, *(uint32_t*)&h1);
    sts8(baseLo + phys, *(uint32_t*)&l0, *(uint32_t*)&l1);
}

// ---------------------------------------------------------------------------
// Kernel 0: routing (robust to int32/int64 selected_experts)
// ---------------------------------------------------------------------------
__global__ void route_kernel(const int* __restrict__ sel32)
{
    __shared__ int cnt[N_EXP];
    __shared__ int cur[N_EXP];
    __shared__ int is64;
    const int tid = threadIdx.x;

    if (tid == 0) is64 = 1;
    if (tid < N_EXP) cnt[tid] = 0;
    __syncthreads();

    for (int p = tid; p < N_PAIR / 2; p += NTHR)
        if (sel32[2 * p + 1] != 0) atomicExch(&is64, 0);
    __syncthreads();

    const int stride = is64 ? 2 : 1;
    for (int p = tid; p < N_PAIR; p += NTHR)
        atomicAdd(&cnt[sel32[(size_t)p * stride] & 15], 1);
    __syncthreads();

    if (tid == 0) {
        int acc = 0;
        for (int e = 0; e < N_EXP; e++) { g_off[e] = acc; cur[e] = acc; acc += cnt[e]; }
        g_off[N_EXP] = acc;
    }
    __syncthreads();

    for (int p = tid; p < N_PAIR; p += NTHR) {
        int e = sel32[(size_t)p * stride] & 15;
        g_pair[atomicAdd(&cur[e], 1)] = p;
    }
}

// ---------------------------------------------------------------------------
// Kernel 1: up-projection, fp16 2-product split.
//   A (x rows) single fp16; B (w0/w1 interleaved, pre-scaled) fp16 hi+lo.
//   acc = A*Bhi + A*Blo. Epilogue: silu(g)*u -> g_hact.
// ---------------------------------------------------------------------------
__global__ __launch_bounds__(NTHR, 2)
void gemm1_kernel(const float* __restrict__ x,  const float* __restrict__ w0,
                  const float* __restrict__ w1, const float* __restrict__ s0,
                  const float* __restrict__ s1)
{
    const int e    = blockIdx.y;
    const int base = g_off[e];
    const int cntE = g_off[e + 1] - base;
    const int m0   = blockIdx.z * CTA_M;
    if (m0 >= cntE) return;
    const int mRows = min(CTA_M, cntE - m0);
    const int i0   = blockIdx.x * 32;      // 32 i per CTA (64 interleaved rows)

    extern __shared__ char dsm[];
    __shared__ int srow[CTA_M];
    const uint32_t sb = (smem_u32(dsm) + 127u) & ~127u;

    const int tid  = threadIdx.x;
    const int wid  = tid >> 5;
    const int lane = tid & 31;

    if (tid < CTA_M) {
        int mm = m0 + tid;
        srow[tid] = (mm < cntE) ? (g_pair[base + mm] / K_TOP) : 0;
    }
    __syncthreads();

    // A loader: 2 threads/row, 32 f32 each; inactive if row is padding
    const int rbA = tid >> 1;
    const int khA = (tid & 1) * 32;
    const bool aAct = (rbA < mRows);
    const float* aSrc = x + (size_t)srow[rbA] * H_DIM + khA;
    // B loader: 4 threads/row, 16 f32 each
    const int rbB = tid >> 2;
    const int khB = (tid & 3) * 16;
    const int irow = i0 + (rbB >> 1);
    const float* bSrc = (rbB & 1)
        ? w1 + ((size_t)(e * I_DIM + irow)) * H_DIM + khB
        : w0 + ((size_t)(e * I_DIM + irow)) * H_DIM + khB;
    const float* sRow = ((rbB & 1) ? s1 : s0)
        + (size_t)(e * (I_DIM / QBS) + (i0 >> 7)) * (H_DIM / QBS);

    // compute mapping: 4 M-warps x 2 N-warps
    const int wm = wid & 3, wn = wid >> 2;
    const int mW = wm * 32, nW = wn * 32;
    const int arow = lane & 15;
    const int ahalf = lane >> 4;
    const int brow = lane & 7;
    const int bhalf = (lane >> 3) & 1;

    const int nMf = (mW < mRows) ? ((mW + 16 < mRows) ? 2 : 1) : 0;

    float acc[2][4][4];
    #pragma unroll
    for (int a = 0; a < 2; a++)
        #pragma unroll
        for (int b = 0; b < 4; b++)
            #pragma unroll
            for (int c = 0; c < 4; c++) acc[a][b][c] = 0.f;

    const int NIT = H_DIM / KI;   // 32
    float4 aReg[8], bReg[4];

    // prologue: iter 0 -> buf 0
    {
        if (aAct) {
            const float4* ap = (const float4*)aSrc;
            #pragma unroll
            for (int q = 0; q < 8; q++) aReg[q] = ap[q];
            #pragma unroll
            for (int q = 0; q < 8; q++)
                cvtA_store(aReg[q], rbA, khA + q * 4, sb);
        }
        const float4* bp = (const float4*)bSrc;
        #pragma unroll
        for (int q = 0; q < 4; q++) bReg[q] = bp[q];
        const float sc = sRow[0];
        #pragma unroll
        for (int q = 0; q < 4; q++) {
            float4 vb = bReg[q];
            vb.x *= sc; vb.y *= sc; vb.z *= sc; vb.w *= sc;
            cvtB_store(vb, rbB, khB + q * 4, sb + ABLK, sb + ABLK + BBLK);
        }
    }
    __syncthreads();

    for (int it = 0; it < NIT; it++) {
        if (it + 1 < NIT) {
            if (aAct) {
                const float4* ap = (const float4*)(aSrc + (it + 1) * KI);
                #pragma unroll
                for (int q = 0; q < 8; q++) aReg[q] = ap[q];
            }
            const float4* bp = (const float4*)(bSrc + (it + 1) * KI);
            #pragma unroll
            for (int q = 0; q < 4; q++) bReg[q] = bp[q];
        }

        const uint32_t bufA = sb + (uint32_t)(it & 1) * BUF_BYTES;
        const uint32_t sbBhi = bufA + ABLK, sbBlo = sbBhi + BBLK;

        if (nMf) {
            #pragma unroll
            for (int ks = 0; ks < 4; ks++) {
                uint32_t aH[2][4], bH[4][2], bL[4][2];
                #pragma unroll
                for (int mf = 0; mf < 2; mf++) if (mf < nMf) {
                    uint32_t row = (uint32_t)(mW + mf * 16 + arow);
                    uint32_t off = row * 128u + ((((uint32_t)(ks * 2 + ahalf)) ^ (row & 7u)) << 4);
                    ldsm_x4(aH[mf], bufA + off);
                }
                #pragma unroll
                for (int nf = 0; nf < 4; nf++) {
                    uint32_t row = (uint32_t)(nW + nf * 8 + brow);
                    uint32_t off = row * 128u + ((((uint32_t)(ks * 2 + bhalf)) ^ (row & 7u)) << 4);
                    ldsm_x2(bH[nf], sbBhi + off);
                    ldsm_x2(bL[nf], sbBlo + off);
                }
                #pragma unroll
                for (int mf = 0; mf < 2; mf++) if (mf < nMf)
                    #pragma unroll
                    for (int nf = 0; nf < 4; nf++) {
                        mma16816f(acc[mf][nf], aH[mf], bH[nf]);
                        mma16816f(acc[mf][nf], aH[mf], bL[nf]);
                    }
            }
        }

        if (it + 1 < NIT) {
            const uint32_t nb = sb + (uint32_t)((it + 1) & 1) * BUF_BYTES;
            const float sc = sRow[(it + 1) >> 1];
            if (aAct) {
                #pragma unroll
                for (int q = 0; q < 8; q++)
                    cvtA_store(aReg[q], rbA, khA + q * 4, nb);
            }
            #pragma unroll
            for (int q = 0; q < 4; q++) {
                float4 vb = bReg[q];
                vb.x *= sc; vb.y *= sc; vb.z *= sc; vb.w *= sc;
                cvtB_store(vb, rbB, khB + q * 4, nb + ABLK, nb + ABLK + BBLK);
            }
        }
        __syncthreads();
    }

    // epilogue: silu(g)*u, col pair (2j,2j+1) = (g,u) for i = i0 + wn*16 + nf*4 + qcol
    const int qrow = lane >> 2;
    const int qcol = lane & 3;
    #pragma unroll
    for (int mf = 0; mf < 2; mf++) if (mf < nMf) {
        const int r0 = mW + mf * 16 + qrow;
        const int r1 = r0 + 8;
        #pragma unroll
        for (int nf = 0; nf < 4; nf++) {
            const int ii = i0 + wn * 16 + nf * 4 + qcol;
            float g0 = acc[mf][nf][0], u0 = acc[mf][nf][1];
            float g1 = acc[mf][nf][2], u1 = acc[mf][nf][3];
            if (r0 < mRows) {
                float s = g0 / (1.0f + __expf(-g0));
                g_hact[(size_t)(base + m0 + r0) * I_DIM + ii] = s * u0;
            }
            if (r1 < mRows) {
                float s = g1 / (1.0f + __expf(-g1));
                g_hact[(size_t)(base + m0 + r1) * I_DIM + ii] = s * u1;
            }
        }
    }
}

// ---------------------------------------------------------------------------
// Kernel 2: down-projection, fp16 2-product split + routing weight scatter.
//   A (hact rows) single fp16; B (w2, pre-scaled) fp16 hi+lo.
// ---------------------------------------------------------------------------
__global__ __launch_bounds__(NTHR, 2)
void gemm2_kernel(const float* __restrict__ w2, const float* __restrict__ s2,
                  const float* __restrict__ rw, float* __restrict__ out)
{
    const int e    = blockIdx.y;
    const int base = g_off[e];
    const int cntE = g_off[e + 1] - base;
    const int m0   = blockIdx.z * CTA_M;
    if (m0 >= cntE) return;
    const int mRows = min(CTA_M, cntE - m0);
    const int n0   = blockIdx.x * CTA_N;

    extern __shared__ char dsm[];
    __shared__ int spair[CTA_M];
    const uint32_t sb = (smem_u32(dsm) + 127u) & ~127u;

    const int tid  = threadIdx.x;
    const int wid  = tid >> 5;
    const int lane = tid & 31;

    if (tid < CTA_M) {
        int mm = m0 + tid;
        spair[tid] = (mm < cntE) ? g_pair[base + mm] : 0;
    }
    __syncthreads();

    const int rbA = tid >> 1;
    const int khA = (tid & 1) * 32;
    const bool aAct = (rbA < mRows);
    const float* aSrc = g_hact + (size_t)(base + m0 + rbA) * I_DIM + khA;
    const int rbB = tid >> 2;
    const int khB = (tid & 3) * 16;
    const float* bSrc = w2 + ((size_t)(e * H_DIM + n0 + rbB)) * I_DIM + khB;
    const float* sRow = s2 + (size_t)(e * (H_DIM / QBS) + (n0 >> 7)) * (I_DIM / QBS);

    const int wm = wid & 3, wn = wid >> 2;
    const int mW = wm * 32, nW = wn * 32;
    const int arow = lane & 15;
    const int ahalf = lane >> 4;
    const int brow = lane & 7;
    const int bhalf = (lane >> 3) & 1;

    const int nMf = (mW < mRows) ? ((mW + 16 < mRows) ? 2 : 1) : 0;

    float acc[2][4][4];
    #pragma unroll
    for (int a = 0; a < 2; a++)
        #pragma unroll
        for (int b = 0; b < 4; b++)
            #pragma unroll
            for (int c = 0; c < 4; c++) acc[a][b][c] = 0.f;

    const int NIT = I_DIM / KI;   // 16
    float4 aReg[8], bReg[4];

    {
        if (aAct) {
            const float4* ap = (const float4*)aSrc;
            #pragma unroll
            for (int q = 0; q < 8; q++) aReg[q] = ap[q];
            #pragma unroll
            for (int q = 0; q < 8; q++)
                cvtA_store(aReg[q], rbA, khA + q * 4, sb);
        }
        const float4* bp = (const float4*)bSrc;
        #pragma unroll
        for (int q = 0; q < 4; q++) bReg[q] = bp[q];
        const float sc = sRow[0];
        #pragma unroll
        for (int q = 0; q < 4; q++) {
            float4 vb = bReg[q];
            vb.x *= sc; vb.y *= sc; vb.z *= sc; vb.w *= sc;
            cvtB_store(vb, rbB, khB + q * 4, sb + ABLK, sb + ABLK + BBLK);
        }
    }
    __syncthreads();

    for (int it = 0; it < NIT; it++) {
        if (it + 1 < NIT) {
            if (aAct) {
                const float4* ap = (const float4*)(aSrc + (it + 1) * KI);
                #pragma unroll
                for (int q = 0; q < 8; q++) aReg[q] = ap[q];
            }
            const float4* bp = (const float4*)(bSrc + (it + 1) * KI);
            #pragma unroll
            for (int q = 0; q < 4; q++) bReg[q] = bp[q];
        }

        const uint32_t bufA = sb + (uint32_t)(it & 1) * BUF_BYTES;
        const uint32_t sbBhi = bufA + ABLK, sbBlo = sbBhi + BBLK;

        if (nMf) {
            #pragma unroll
            for (int ks = 0; ks < 4; ks++) {
                uint32_t aH[2][4], bH[4][2], bL[4][2];
                #pragma unroll
                for (int mf = 0; mf < 2; mf++) if (mf < nMf) {
                    uint32_t row = (uint32_t)(mW + mf * 16 + arow);
                    uint32_t off = row * 128u + ((((uint32_t)(ks * 2 + ahalf)) ^ (row & 7u)) << 4);
                    ldsm_x4(aH[mf], bufA + off);
                }
                #pragma unroll
                for (int nf = 0; nf < 4; nf++) {
                    uint32_t row = (uint32_t)(nW + nf * 8 + brow);
                    uint32_t off = row * 128u + ((((uint32_t)(ks * 2 + bhalf)) ^ (row & 7u)) << 4);
                    ldsm_x2(bH[nf], sbBhi + off);
                    ldsm_x2(bL[nf], sbBlo + off);
                }
                #pragma unroll
                for (int mf = 0; mf < 2; mf++) if (mf < nMf)
                    #pragma unroll
                    for (int nf = 0; nf < 4; nf++) {
                        mma16816f(acc[mf][nf], aH[mf], bH[nf]);
                        mma16816f(acc[mf][nf], aH[mf], bL[nf]);
                    }
            }
        }

        if (it + 1 < NIT) {
            const uint32_t nb = sb + (uint32_t)((it + 1) & 1) * BUF_BYTES;
            const float sc = sRow[(it + 1) >> 1];
            if (aAct) {
                #pragma unroll
                for (int q = 0; q < 8; q++)
                    cvtA_store(aReg[q], rbA, khA + q * 4, nb);
            }
            #pragma unroll
            for (int q = 0; q < 4; q++) {
                float4 vb = bReg[q];
                vb.x *= sc; vb.y *= sc; vb.z *= sc; vb.w *= sc;
                cvtB_store(vb, rbB, khB + q * 4, nb + ABLK, nb + ABLK + BBLK);
            }
        }
        __syncthreads();
    }

    // epilogue: routing weight, scatter
    const int qrow = lane >> 2;
    const int qcol = lane & 3;
    #pragma unroll
    for (int mf = 0; mf < 2; mf++) if (mf < nMf) {
        const int r0 = mW + mf * 16 + qrow;
        const int r1 = r0 + 8;
        const int pid0 = spair[r0];
        const int pid1 = spair[r1];
        const float w0g = rw[pid0];
        const float w1g = rw[pid1];
        #pragma unroll
        for (int nf = 0; nf < 4; nf++) {
            const int col = n0 + nW + nf * 8 + qcol * 2;
            if (r0 < mRows) {
                float2 v = { acc[mf][nf][0] * w0g, acc[mf][nf][1] * w0g };
                *(float2*)&out[(size_t)pid0 * H_DIM + col] = v;
            }
            if (r1 < mRows) {
                float2 v = { acc[mf][nf][2] * w1g, acc[mf][nf][3] * w1g };
                *(float2*)&out[(size_t)pid1 * H_DIM + col] = v;
            }
        }
    }
}

// ---------------------------------------------------------------------------
// Launch
// ---------------------------------------------------------------------------
extern "C" void kernel_launch(void* const* d_in, const int* in_sizes, int n_in,
                              void* d_out, int out_size)
{
    const float* x   = (const float*)d_in[0];
    const float* w0  = (const float*)d_in[1];
    const float* w1  = (const float*)d_in[2];
    const float* w2  = (const float*)d_in[3];
    const float* s0  = (const float*)d_in[4];
    const float* s1  = (const float*)d_in[5];
    const float* s2  = (const float*)d_in[6];
    const int*   sel = (const int*)  d_in[7];
    const float* rw  = (const float*)d_in[8];
    float*       out = (float*)d_out;

    cudaFuncSetAttribute(gemm1_kernel, cudaFuncAttributeMaxDynamicSharedMemorySize, SMEM_DYN);
    cudaFuncSetAttribute(gemm2_kernel, cudaFuncAttributeMaxDynamicSharedMemorySize, SMEM_DYN);

    route_kernel<<<1, NTHR>>>(sel);

    dim3 g1(I_DIM / 32, N_EXP, N_PAIR / CTA_M);    // 32 x 16 x 16 (z early-exits)
    gemm1_kernel<<<g1, NTHR, SMEM_DYN>>>(x, w0, w1, s0, s1);

    dim3 g2(H_DIM / CTA_N, N_EXP, N_PAIR / CTA_M); // 32 x 16 x 16
    gemm2_kernel<<<g2, NTHR, SMEM_DYN>>>(w2, s2, rw, out);
}

// round 17
// speedup vs baseline: 1.8464x; 1.3827x over previous
#include <cuda_runtime.h>
#include <cuda_fp16.h>
#include <cstdint>

// Problem constants
#define T_TOK   512
#define H_DIM   2048
#define I_DIM   1024
#define N_EXP   16
#define K_TOP   4
#define N_PAIR  (T_TOK * K_TOP)
#define QBS     128

#define CTA_M   128
#define CTA_N   64
#define KI      64        // K elems per iteration
#define NTHR    256

// SMEM: A single fp16 block (128 x 128B); B split hi/lo (64 x 128B each)
#define ABLK    16384
#define BBLK    8192
#define BUF_BYTES  (ABLK + 2*BBLK)          // 32KB
#define SMEM_DYN   (2*BUF_BYTES + 256)      // double buffer ~64.25KB

// ---------------------------------------------------------------------------
// Scratch
// ---------------------------------------------------------------------------
__device__ int   g_off[N_EXP + 1];
__device__ int   g_pair[N_PAIR];
__device__ __align__(16) __half g_x16[T_TOK * H_DIM];              // x pre-converted
__device__ __align__(16) __half g_hact[(N_PAIR + CTA_M) * I_DIM];  // fp16 hact

// ---------------------------------------------------------------------------
// Helpers
// ---------------------------------------------------------------------------
__device__ __forceinline__ uint32_t smem_u32(const void* p) {
    uint32_t a;
    asm("{ .reg .u64 t; cvta.to.shared.u64 t, %1; cvt.u32.u64 %0, t; }" : "=r"(a) : "l"(p));
    return a;
}

__device__ __forceinline__ void ldsm_x4(uint32_t* r, uint32_t addr) {
    asm volatile("ldmatrix.sync.aligned.m8n8.x4.shared.b16 {%0,%1,%2,%3}, [%4];"
        : "=r"(r[0]), "=r"(r[1]), "=r"(r[2]), "=r"(r[3]) : "r"(addr));
}

__device__ __forceinline__ void mma16816f(float* c, const uint32_t* a, const uint32_t* b) {
    asm volatile(
        "mma.sync.aligned.m16n8k16.row.col.f32.f16.f16.f32 "
        "{%0,%1,%2,%3}, {%4,%5,%6,%7}, {%8,%9}, {%0,%1,%2,%3};"
        : "+f"(c[0]), "+f"(c[1]), "+f"(c[2]), "+f"(c[3])
        : "r"(a[0]), "r"(a[1]), "r"(a[2]), "r"(a[3]), "r"(b[0]), "r"(b[1]));
}

__device__ __forceinline__ void sts8(uint32_t addr, uint32_t v0, uint32_t v1) {
    asm volatile("st.shared.v2.b32 [%0], {%1,%2};" :: "r"(addr), "r"(v0), "r"(v1) : "memory");
}
__device__ __forceinline__ void sts16(uint32_t addr, uint4 v) {
    asm volatile("st.shared.v4.b32 [%0], {%1,%2,%3,%4};"
        :: "r"(addr), "r"(v.x), "r"(v.y), "r"(v.z), "r"(v.w) : "memory");
}

// swizzled byte offset; k0 counted in fp16 elements (8 per 16B chunk)
__device__ __forceinline__ uint32_t swzoff(int rb, int k0) {
    uint32_t chunk = (uint32_t)(k0 >> 3);
    return (uint32_t)rb * 128u + ((chunk ^ ((uint32_t)rb & 7u)) << 4) + ((k0 & 4) << 1);
}

// B: fp32x4 -> fp16 hi quad + fp16 lo (residual) quad
__device__ __forceinline__ void cvtB_store(float4 v, int rb, int k0,
                                           uint32_t baseHi, uint32_t baseLo) {
    uint32_t phys = swzoff(rb, k0);
    __half2 h0 = __floats2half2_rn(v.x, v.y);
    __half2 h1 = __floats2half2_rn(v.z, v.w);
    float rx = v.x - __half2float(__low2half(h0));
    float ry = v.y - __half2float(__high2half(h0));
    float rz = v.z - __half2float(__low2half(h1));
    float rw = v.w - __half2float(__high2half(h1));
    __half2 l0 = __floats2half2_rn(rx, ry);
    __half2 l1 = __floats2half2_rn(rz, rw);
    sts8(baseHi + phys, *(uint32_t*)&h0, *(uint32_t*)&h1);
    sts8(baseLo + phys, *(uint32_t*)&l0, *(uint32_t*)&l1);
}

// ---------------------------------------------------------------------------
// Kernel X: x fp32 -> fp16 (one-time)
// ---------------------------------------------------------------------------
__global__ void xcvt_kernel(const float* __restrict__ x)
{
    const int idx = (blockIdx.x * NTHR + threadIdx.x) * 8;   // 8 elems/thread
    float4 v0 = *(const float4*)(x + idx);
    float4 v1 = *(const float4*)(x + idx + 4);
    __half2 h[4];
    h[0] = __floats2half2_rn(v0.x, v0.y);
    h[1] = __floats2half2_rn(v0.z, v0.w);
    h[2] = __floats2half2_rn(v1.x, v1.y);
    h[3] = __floats2half2_rn(v1.z, v1.w);
    *(uint4*)(g_x16 + idx) = *(uint4*)h;
}

// ---------------------------------------------------------------------------
// Kernel 0: routing (robust to int32/int64 selected_experts)
// ---------------------------------------------------------------------------
__global__ void route_kernel(const int* __restrict__ sel32)
{
    __shared__ int cnt[N_EXP];
    __shared__ int cur[N_EXP];
    __shared__ int is64;
    const int tid = threadIdx.x;

    if (tid == 0) is64 = 1;
    if (tid < N_EXP) cnt[tid] = 0;
    __syncthreads();

    for (int p = tid; p < N_PAIR / 2; p += NTHR)
        if (sel32[2 * p + 1] != 0) atomicExch(&is64, 0);
    __syncthreads();

    const int stride = is64 ? 2 : 1;
    for (int p = tid; p < N_PAIR; p += NTHR)
        atomicAdd(&cnt[sel32[(size_t)p * stride] & 15], 1);
    __syncthreads();

    if (tid == 0) {
        int acc = 0;
        for (int e = 0; e < N_EXP; e++) { g_off[e] = acc; cur[e] = acc; acc += cnt[e]; }
        g_off[N_EXP] = acc;
    }
    __syncthreads();

    for (int p = tid; p < N_PAIR; p += NTHR) {
        int e = sel32[(size_t)p * stride] & 15;
        g_pair[atomicAdd(&cur[e], 1)] = p;
    }
}

// ---------------------------------------------------------------------------
// Kernel 1: up-projection, fp16 2-product split (A pre-converted fp16).
// ---------------------------------------------------------------------------
__global__ __launch_bounds__(NTHR, 2)
void gemm1_kernel(const float* __restrict__ w0, const float* __restrict__ w1,
                  const float* __restrict__ s0, const float* __restrict__ s1)
{
    const int e    = blockIdx.y;
    const int base = g_off[e];
    const int cntE = g_off[e + 1] - base;
    const int m0   = blockIdx.z * CTA_M;
    if (m0 >= cntE) return;
    const int mRows = min(CTA_M, cntE - m0);
    const int i0   = blockIdx.x * 32;      // 32 i per CTA (64 interleaved rows)

    extern __shared__ char dsm[];
    __shared__ int srow[CTA_M];
    const uint32_t sb = (smem_u32(dsm) + 127u) & ~127u;

    const int tid  = threadIdx.x;
    const int wid  = tid >> 5;
    const int lane = tid & 31;

    if (tid < CTA_M) {
        int mm = m0 + tid;
        srow[tid] = (mm < cntE) ? (g_pair[base + mm] / K_TOP) : 0;
    }
    __syncthreads();

    // A loader: 2 threads/row, 32 fp16 each (4 x 16B)
    const int rbA = tid >> 1;
    const int khA = (tid & 1) * 32;
    const bool aAct = (rbA < mRows);
    const __half* aSrc = g_x16 + (size_t)srow[rbA] * H_DIM + khA;
    // B loader: 4 threads/row, 16 f32 each
    const int rbB = tid >> 2;
    const int khB = (tid & 3) * 16;
    const int irow = i0 + (rbB >> 1);
    const float* bSrc = (rbB & 1)
        ? w1 + ((size_t)(e * I_DIM + irow)) * H_DIM + khB
        : w0 + ((size_t)(e * I_DIM + irow)) * H_DIM + khB;
    const float* sRow = ((rbB & 1) ? s1 : s0)
        + (size_t)(e * (I_DIM / QBS) + (i0 >> 7)) * (H_DIM / QBS);

    // compute mapping: 4 M-warps x 2 N-warps
    const int wm = wid & 3, wn = wid >> 2;
    const int mW = wm * 32, nW = wn * 32;
    const int arow = lane & 15;
    const int ahalf = lane >> 4;
    // B x4 lane map: row covers 16 N-rows (nf pair), chunk selects k-half
    const int brow4 = ((lane >> 4) << 3) + (lane & 7);
    const int bsel4 = (lane >> 3) & 1;

    const int nMf = (mW < mRows) ? ((mW + 16 < mRows) ? 2 : 1) : 0;

    float acc[2][4][4];
    #pragma unroll
    for (int a = 0; a < 2; a++)
        #pragma unroll
        for (int b = 0; b < 4; b++)
            #pragma unroll
            for (int c = 0; c < 4; c++) acc[a][b][c] = 0.f;

    const int NIT = H_DIM / KI;   // 32
    uint4 aReg[4];
    float4 bReg[4];

    // prologue: iter 0 -> buf 0
    {
        if (aAct) {
            const uint4* ap = (const uint4*)aSrc;
            #pragma unroll
            for (int q = 0; q < 4; q++) aReg[q] = ap[q];
            #pragma unroll
            for (int q = 0; q < 4; q++)
                sts16(sb + swzoff(rbA, khA + q * 8), aReg[q]);
        }
        const float4* bp = (const float4*)bSrc;
        #pragma unroll
        for (int q = 0; q < 4; q++) bReg[q] = bp[q];
        const float sc = sRow[0];
        #pragma unroll
        for (int q = 0; q < 4; q++) {
            float4 vb = bReg[q];
            vb.x *= sc; vb.y *= sc; vb.z *= sc; vb.w *= sc;
            cvtB_store(vb, rbB, khB + q * 4, sb + ABLK, sb + ABLK + BBLK);
        }
    }
    __syncthreads();

    for (int it = 0; it < NIT; it++) {
        if (it + 1 < NIT) {
            if (aAct) {
                const uint4* ap = (const uint4*)(aSrc + (it + 1) * KI);
                #pragma unroll
                for (int q = 0; q < 4; q++) aReg[q] = ap[q];
            }
            const float4* bp = (const float4*)(bSrc + (it + 1) * KI);
            #pragma unroll
            for (int q = 0; q < 4; q++) bReg[q] = bp[q];
        }

        const uint32_t bufA = sb + (uint32_t)(it & 1) * BUF_BYTES;
        const uint32_t sbBhi = bufA + ABLK, sbBlo = sbBhi + BBLK;

        if (nMf) {
            #pragma unroll
            for (int ks = 0; ks < 4; ks++) {
                uint32_t aH[2][4], bH[2][4], bL[2][4];
                #pragma unroll
                for (int mf = 0; mf < 2; mf++) if (mf < nMf) {
                    uint32_t row = (uint32_t)(mW + mf * 16 + arow);
                    uint32_t off = row * 128u + ((((uint32_t)(ks * 2 + ahalf)) ^ (row & 7u)) << 4);
                    ldsm_x4(aH[mf], bufA + off);
                }
                #pragma unroll
                for (int p = 0; p < 2; p++) {
                    uint32_t row = (uint32_t)(nW + p * 16 + brow4);
                    uint32_t off = row * 128u + ((((uint32_t)(ks * 2 + bsel4)) ^ (row & 7u)) << 4);
                    ldsm_x4(bH[p], sbBhi + off);
                    ldsm_x4(bL[p], sbBlo + off);
                }
                #pragma unroll
                for (int mf = 0; mf < 2; mf++) if (mf < nMf)
                    #pragma unroll
                    for (int p = 0; p < 2; p++) {
                        mma16816f(acc[mf][2*p],   aH[mf], &bH[p][0]);
                        mma16816f(acc[mf][2*p],   aH[mf], &bL[p][0]);
                        mma16816f(acc[mf][2*p+1], aH[mf], &bH[p][2]);
                        mma16816f(acc[mf][2*p+1], aH[mf], &bL[p][2]);
                    }
            }
        }

        if (it + 1 < NIT) {
            const uint32_t nb = sb + (uint32_t)((it + 1) & 1) * BUF_BYTES;
            const float sc = sRow[(it + 1) >> 1];
            if (aAct) {
                #pragma unroll
                for (int q = 0; q < 4; q++)
                    sts16(nb + swzoff(rbA, khA + q * 8), aReg[q]);
            }
            #pragma unroll
            for (int q = 0; q < 4; q++) {
                float4 vb = bReg[q];
                vb.x *= sc; vb.y *= sc; vb.z *= sc; vb.w *= sc;
                cvtB_store(vb, rbB, khB + q * 4, nb + ABLK, nb + ABLK + BBLK);
            }
        }
        __syncthreads();
    }

    // epilogue: silu(g)*u -> fp16 hact
    const int qrow = lane >> 2;
    const int qcol = lane & 3;
    #pragma unroll
    for (int mf = 0; mf < 2; mf++) if (mf < nMf) {
        const int r0 = mW + mf * 16 + qrow;
        const int r1 = r0 + 8;
        #pragma unroll
        for (int nf = 0; nf < 4; nf++) {
            const int ii = i0 + wn * 16 + nf * 4 + qcol;
            float g0 = acc[mf][nf][0], u0 = acc[mf][nf][1];
            float g1 = acc[mf][nf][2], u1 = acc[mf][nf][3];
            if (r0 < mRows) {
                float s = g0 / (1.0f + __expf(-g0));
                g_hact[(size_t)(base + m0 + r0) * I_DIM + ii] = __float2half(s * u0);
            }
            if (r1 < mRows) {
                float s = g1 / (1.0f + __expf(-g1));
                g_hact[(size_t)(base + m0 + r1) * I_DIM + ii] = __float2half(s * u1);
            }
        }
    }
}

// ---------------------------------------------------------------------------
// Kernel 2: down-projection (A = fp16 hact direct) + routing weight scatter.
// ---------------------------------------------------------------------------
__global__ __launch_bounds__(NTHR, 2)
void gemm2_kernel(const float* __restrict__ w2, const float* __restrict__ s2,
                  const float* __restrict__ rw, float* __restrict__ out)
{
    const int e    = blockIdx.y;
    const int base = g_off[e];
    const int cntE = g_off[e + 1] - base;
    const int m0   = blockIdx.z * CTA_M;
    if (m0 >= cntE) return;
    const int mRows = min(CTA_M, cntE - m0);
    const int n0   = blockIdx.x * CTA_N;

    extern __shared__ char dsm[];
    __shared__ int spair[CTA_M];
    const uint32_t sb = (smem_u32(dsm) + 127u) & ~127u;

    const int tid  = threadIdx.x;
    const int wid  = tid >> 5;
    const int lane = tid & 31;

    if (tid < CTA_M) {
        int mm = m0 + tid;
        spair[tid] = (mm < cntE) ? g_pair[base + mm] : 0;
    }
    __syncthreads();

    const int rbA = tid >> 1;
    const int khA = (tid & 1) * 32;
    const bool aAct = (rbA < mRows);
    const __half* aSrc = g_hact + (size_t)(base + m0 + rbA) * I_DIM + khA;
    const int rbB = tid >> 2;
    const int khB = (tid & 3) * 16;
    const float* bSrc = w2 + ((size_t)(e * H_DIM + n0 + rbB)) * I_DIM + khB;
    const float* sRow = s2 + (size_t)(e * (H_DIM / QBS) + (n0 >> 7)) * (I_DIM / QBS);

    const int wm = wid & 3, wn = wid >> 2;
    const int mW = wm * 32, nW = wn * 32;
    const int arow = lane & 15;
    const int ahalf = lane >> 4;
    const int brow4 = ((lane >> 4) << 3) + (lane & 7);
    const int bsel4 = (lane >> 3) & 1;

    const int nMf = (mW < mRows) ? ((mW + 16 < mRows) ? 2 : 1) : 0;

    float acc[2][4][4];
    #pragma unroll
    for (int a = 0; a < 2; a++)
        #pragma unroll
        for (int b = 0; b < 4; b++)
            #pragma unroll
            for (int c = 0; c < 4; c++) acc[a][b][c] = 0.f;

    const int NIT = I_DIM / KI;   // 16
    uint4 aReg[4];
    float4 bReg[4];

    {
        if (aAct) {
            const uint4* ap = (const uint4*)aSrc;
            #pragma unroll
            for (int q = 0; q < 4; q++) aReg[q] = ap[q];
            #pragma unroll
            for (int q = 0; q < 4; q++)
                sts16(sb + swzoff(rbA, khA + q * 8), aReg[q]);
        }
        const float4* bp = (const float4*)bSrc;
        #pragma unroll
        for (int q = 0; q < 4; q++) bReg[q] = bp[q];
        const float sc = sRow[0];
        #pragma unroll
        for (int q = 0; q < 4; q++) {
            float4 vb = bReg[q];
            vb.x *= sc; vb.y *= sc; vb.z *= sc; vb.w *= sc;
            cvtB_store(vb, rbB, khB + q * 4, sb + ABLK, sb + ABLK + BBLK);
        }
    }
    __syncthreads();

    for (int it = 0; it < NIT; it++) {
        if (it + 1 < NIT) {
            if (aAct) {
                const uint4* ap = (const uint4*)(aSrc + (it + 1) * KI);
                #pragma unroll
                for (int q = 0; q < 4; q++) aReg[q] = ap[q];
            }
            const float4* bp = (const float4*)(bSrc + (it + 1) * KI);
            #pragma unroll
            for (int q = 0; q < 4; q++) bReg[q] = bp[q];
        }

        const uint32_t bufA = sb + (uint32_t)(it & 1) * BUF_BYTES;
        const uint32_t sbBhi = bufA + ABLK, sbBlo = sbBhi + BBLK;

        if (nMf) {
            #pragma unroll
            for (int ks = 0; ks < 4; ks++) {
                uint32_t aH[2][4], bH[2][4], bL[2][4];
                #pragma unroll
                for (int mf = 0; mf < 2; mf++) if (mf < nMf) {
                    uint32_t row = (uint32_t)(mW + mf * 16 + arow);
                    uint32_t off = row * 128u + ((((uint32_t)(ks * 2 + ahalf)) ^ (row & 7u)) << 4);
                    ldsm_x4(aH[mf], bufA + off);
                }
                #pragma unroll
                for (int p = 0; p < 2; p++) {
                    uint32_t row = (uint32_t)(nW + p * 16 + brow4);
                    uint32_t off = row * 128u + ((((uint32_t)(ks * 2 + bsel4)) ^ (row & 7u)) << 4);
                    ldsm_x4(bH[p], sbBhi + off);
                    ldsm_x4(bL[p], sbBlo + off);
                }
                #pragma unroll
                for (int mf = 0; mf < 2; mf++) if (mf < nMf)
                    #pragma unroll
                    for (int p = 0; p < 2; p++) {
                        mma16816f(acc[mf][2*p],   aH[mf], &bH[p][0]);
                        mma16816f(acc[mf][2*p],   aH[mf], &bL[p][0]);
                        mma16816f(acc[mf][2*p+1], aH[mf], &bH[p][2]);
                        mma16816f(acc[mf][2*p+1], aH[mf], &bL[p][2]);
                    }
            }
        }

        if (it + 1 < NIT) {
            const uint32_t nb = sb + (uint32_t)((it + 1) & 1) * BUF_BYTES;
            const float sc = sRow[(it + 1) >> 1];
            if (aAct) {
                #pragma unroll
                for (int q = 0; q < 4; q++)
                    sts16(nb + swzoff(rbA, khA + q * 8), aReg[q]);
            }
            #pragma unroll
            for (int q = 0; q < 4; q++) {
                float4 vb = bReg[q];
                vb.x *= sc; vb.y *= sc; vb.z *= sc; vb.w *= sc;
                cvtB_store(vb, rbB, khB + q * 4, nb + ABLK, nb + ABLK + BBLK);
            }
        }
        __syncthreads();
    }

    // epilogue: routing weight, scatter
    const int qrow = lane >> 2;
    const int qcol = lane & 3;
    #pragma unroll
    for (int mf = 0; mf < 2; mf++) if (mf < nMf) {
        const int r0 = mW + mf * 16 + qrow;
        const int r1 = r0 + 8;
        const int pid0 = spair[r0];
        const int pid1 = spair[r1];
        const float w0g = rw[pid0];
        const float w1g = rw[pid1];
        #pragma unroll
        for (int nf = 0; nf < 4; nf++) {
            const int col = n0 + nW + nf * 8 + qcol * 2;
            if (r0 < mRows) {
                float2 v = { acc[mf][nf][0] * w0g, acc[mf][nf][1] * w0g };
                *(float2*)&out[(size_t)pid0 * H_DIM + col] = v;
            }
            if (r1 < mRows) {
                float2 v = { acc[mf][nf][2] * w1g, acc[mf][nf][3] * w1g };
                *(float2*)&out[(size_t)pid1 * H_DIM + col] = v;
            }
        }
    }
}

// ---------------------------------------------------------------------------
// Launch
// ---------------------------------------------------------------------------
extern "C" void kernel_launch(void* const* d_in, const int* in_sizes, int n_in,
                              void* d_out, int out_size)
{
    const float* x   = (const float*)d_in[0];
    const float* w0  = (const float*)d_in[1];
    const float* w1  = (const float*)d_in[2];
    const float* w2  = (const float*)d_in[3];
    const float* s0  = (const float*)d_in[4];
    const float* s1  = (const float*)d_in[5];
    const float* s2  = (const float*)d_in[6];
    const int*   sel = (const int*)  d_in[7];
    const float* rw  = (const float*)d_in[8];
    float*       out = (float*)d_out;

    cudaFuncSetAttribute(gemm1_kernel, cudaFuncAttributeMaxDynamicSharedMemorySize, SMEM_DYN);
    cudaFuncSetAttribute(gemm2_kernel, cudaFuncAttributeMaxDynamicSharedMemorySize, SMEM_DYN);

    xcvt_kernel<<<(T_TOK * H_DIM) / (NTHR * 8), NTHR>>>(x);
    route_kernel<<<1, NTHR>>>(sel);

    dim3 g1(I_DIM / 32, N_EXP, N_PAIR / CTA_M);    // 32 x 16 x 16 (z early-exits)
    gemm1_kernel<<<g1, NTHR, SMEM_DYN>>>(w0, w1, s0, s1);

    dim3 g2(H_DIM / CTA_N, N_EXP, N_PAIR / CTA_M); // 32 x 16 x 16
    gemm2_kernel<<<g2, NTHR, SMEM_DYN>>>(w2, s2, rw, out);
}